// round 1
// baseline (speedup 1.0000x reference)
#include <cuda_runtime.h>
#include <math.h>

// Problem dims (fixed by the reference)
#define B_   2
#define C_   32
#define CP1  33
#define W_   256
#define H_   256
#define X_   512
#define Y_   512

// GEMM tiling
#define BM 128
#define BN 128
#define BK 8
#define TM 8
#define TN 8
#define NTHREADS 256

// Scratch: static __device__ arrays (no allocation allowed in kernel_launch)
__device__ float g_wlon[B_ * X_ * W_];                 // [b][x][w]  (w_lon transposed) ~1 MB
__device__ float g_wlat[B_ * H_ * Y_];                 // [b][h][y]                      ~1 MB
__device__ float g_tmp[(size_t)B_ * CP1 * X_ * H_];    // [b][c][x][h]                   ~34.6 MB

// ---------------------------------------------------------------------------
// RBF weights: w_lon[b][x][w] = exp(-0.5*(xin_lon[b,w]-xout_lon[b,x])^2/ls^2)
//              w_lat[b][h][y] = exp(-0.5*(xin_lat[b,h]-xout_lat[b,y])^2/ls^2)
// ---------------------------------------------------------------------------
__global__ void rbf_kernel(const float* __restrict__ xin_lon,
                           const float* __restrict__ xin_lat,
                           const float* __restrict__ xout_lon,
                           const float* __restrict__ xout_lat,
                           const float* __restrict__ init_ls) {
    const float ls  = init_ls[0];
    const float inv = -0.5f / (ls * ls);
    const int NLON = B_ * X_ * W_;
    const int NLAT = B_ * H_ * Y_;
    int idx = blockIdx.x * blockDim.x + threadIdx.x;
    if (idx < NLON) {
        int w = idx % W_;
        int x = (idx / W_) % X_;
        int b = idx / (W_ * X_);
        float d = xin_lon[b * W_ + w] - xout_lon[b * X_ + x];
        g_wlon[idx] = __expf(inv * d * d);
    } else if (idx < NLON + NLAT) {
        int i = idx - NLON;
        int y = i % Y_;
        int h = (i / Y_) % H_;
        int b = i / (Y_ * H_);
        float d = xin_lat[b * H_ + h] - xout_lat[b * Y_ + y];
        g_wlat[i] = __expf(inv * d * d);
    }
}

// ---------------------------------------------------------------------------
// Stage A: tmp[bc][x][h] = sum_w wlon[b][x][w] * wt_full[b][c][w][h]
//   wt_full channel 0 = density (isnan(wt[b,0,w,h]) ? 0 : 1)
//   wt_full channel c>=1 = nan_to_num(wt[b,c-1,w,h])
// M=X_(512), N=H_(256), K=W_(256)
// ---------------------------------------------------------------------------
__global__ __launch_bounds__(NTHREADS)
void gemm_stageA(const float* __restrict__ wt) {
    const int bc = blockIdx.z;
    const int b  = bc / CP1;
    const int c  = bc % CP1;
    const int x0 = blockIdx.y * BM;
    const int h0 = blockIdx.x * BN;

    const float* __restrict__ A    = g_wlon + (size_t)b * X_ * W_;                     // [X][W]
    const float* __restrict__ Bsrc = wt + ((size_t)b * C_ + (c == 0 ? 0 : (c - 1))) * W_ * H_; // [W][H]
    float* __restrict__ Cout       = g_tmp + (size_t)bc * X_ * H_;                     // [X][H]

    __shared__ float As[BK][BM];
    __shared__ float Bs[BK][BN];

    const int tid = threadIdx.x;
    // A-tile load mapping: 128 rows x 8 cols -> thread: row=tid/2, 4 cols @ (tid&1)*4
    const int arow = tid >> 1;
    const int acol = (tid & 1) * 4;
    // B-tile load mapping: 8 rows x 128 cols -> row=tid/32, 4 cols @ (tid&31)*4
    const int brow = tid >> 5;
    const int bcol = (tid & 31) * 4;
    // compute mapping: 16x16 thread grid, 8x8 per thread
    const int trow = (tid >> 4) * TM;
    const int tcol = (tid & 15) * TN;

    float acc[TM][TN];
#pragma unroll
    for (int i = 0; i < TM; i++)
#pragma unroll
        for (int j = 0; j < TN; j++) acc[i][j] = 0.0f;

    const bool isDens = (c == 0);

    for (int k0 = 0; k0 < W_; k0 += BK) {
        // Load A tile (transposed into smem)
        float4 av = *reinterpret_cast<const float4*>(&A[(size_t)(x0 + arow) * W_ + k0 + acol]);
        As[acol + 0][arow] = av.x;
        As[acol + 1][arow] = av.y;
        As[acol + 2][arow] = av.z;
        As[acol + 3][arow] = av.w;

        // Load B tile with NaN / density transform
        float4 bv = *reinterpret_cast<const float4*>(&Bsrc[(size_t)(k0 + brow) * H_ + h0 + bcol]);
        if (isDens) {
            bv.x = (bv.x != bv.x) ? 0.0f : 1.0f;
            bv.y = (bv.y != bv.y) ? 0.0f : 1.0f;
            bv.z = (bv.z != bv.z) ? 0.0f : 1.0f;
            bv.w = (bv.w != bv.w) ? 0.0f : 1.0f;
        } else {
            bv.x = (bv.x != bv.x) ? 0.0f : bv.x;
            bv.y = (bv.y != bv.y) ? 0.0f : bv.y;
            bv.z = (bv.z != bv.z) ? 0.0f : bv.z;
            bv.w = (bv.w != bv.w) ? 0.0f : bv.w;
        }
        *reinterpret_cast<float4*>(&Bs[brow][bcol]) = bv;

        __syncthreads();

#pragma unroll
        for (int kk = 0; kk < BK; kk++) {
            float4 a0 = *reinterpret_cast<const float4*>(&As[kk][trow]);
            float4 a1 = *reinterpret_cast<const float4*>(&As[kk][trow + 4]);
            float4 b0 = *reinterpret_cast<const float4*>(&Bs[kk][tcol]);
            float4 b1 = *reinterpret_cast<const float4*>(&Bs[kk][tcol + 4]);
            float a[TM] = {a0.x, a0.y, a0.z, a0.w, a1.x, a1.y, a1.z, a1.w};
            float bb[TN] = {b0.x, b0.y, b0.z, b0.w, b1.x, b1.y, b1.z, b1.w};
#pragma unroll
            for (int i = 0; i < TM; i++)
#pragma unroll
                for (int j = 0; j < TN; j++) acc[i][j] += a[i] * bb[j];
        }
        __syncthreads();
    }

#pragma unroll
    for (int i = 0; i < TM; i++) {
        float4 v0 = make_float4(acc[i][0], acc[i][1], acc[i][2], acc[i][3]);
        float4 v1 = make_float4(acc[i][4], acc[i][5], acc[i][6], acc[i][7]);
        *reinterpret_cast<float4*>(&Cout[(size_t)(x0 + trow + i) * H_ + h0 + tcol])     = v0;
        *reinterpret_cast<float4*>(&Cout[(size_t)(x0 + trow + i) * H_ + h0 + tcol + 4]) = v1;
    }
}

// ---------------------------------------------------------------------------
// Stage B: out[bc][x][y] = sum_h tmp[bc][x][h] * wlat[b][h][y]
// M=X_(512), N=Y_(512), K=H_(256)
// ---------------------------------------------------------------------------
__global__ __launch_bounds__(NTHREADS)
void gemm_stageB(float* __restrict__ out) {
    const int bc = blockIdx.z;
    const int b  = bc / CP1;
    const int x0 = blockIdx.y * BM;
    const int y0 = blockIdx.x * BN;

    const float* __restrict__ A    = g_tmp + (size_t)bc * X_ * H_;   // [X][H]
    const float* __restrict__ Bsrc = g_wlat + (size_t)b * H_ * Y_;   // [H][Y]
    float* __restrict__ Cout       = out + (size_t)bc * X_ * Y_;     // [X][Y]

    __shared__ float As[BK][BM];
    __shared__ float Bs[BK][BN];

    const int tid = threadIdx.x;
    const int arow = tid >> 1;
    const int acol = (tid & 1) * 4;
    const int brow = tid >> 5;
    const int bcol = (tid & 31) * 4;
    const int trow = (tid >> 4) * TM;
    const int tcol = (tid & 15) * TN;

    float acc[TM][TN];
#pragma unroll
    for (int i = 0; i < TM; i++)
#pragma unroll
        for (int j = 0; j < TN; j++) acc[i][j] = 0.0f;

    for (int k0 = 0; k0 < H_; k0 += BK) {
        float4 av = *reinterpret_cast<const float4*>(&A[(size_t)(x0 + arow) * H_ + k0 + acol]);
        As[acol + 0][arow] = av.x;
        As[acol + 1][arow] = av.y;
        As[acol + 2][arow] = av.z;
        As[acol + 3][arow] = av.w;

        float4 bv = *reinterpret_cast<const float4*>(&Bsrc[(size_t)(k0 + brow) * Y_ + y0 + bcol]);
        *reinterpret_cast<float4*>(&Bs[brow][bcol]) = bv;

        __syncthreads();

#pragma unroll
        for (int kk = 0; kk < BK; kk++) {
            float4 a0 = *reinterpret_cast<const float4*>(&As[kk][trow]);
            float4 a1 = *reinterpret_cast<const float4*>(&As[kk][trow + 4]);
            float4 b0 = *reinterpret_cast<const float4*>(&Bs[kk][tcol]);
            float4 b1 = *reinterpret_cast<const float4*>(&Bs[kk][tcol + 4]);
            float a[TM] = {a0.x, a0.y, a0.z, a0.w, a1.x, a1.y, a1.z, a1.w};
            float bb[TN] = {b0.x, b0.y, b0.z, b0.w, b1.x, b1.y, b1.z, b1.w};
#pragma unroll
            for (int i = 0; i < TM; i++)
#pragma unroll
                for (int j = 0; j < TN; j++) acc[i][j] += a[i] * bb[j];
        }
        __syncthreads();
    }

#pragma unroll
    for (int i = 0; i < TM; i++) {
        float4 v0 = make_float4(acc[i][0], acc[i][1], acc[i][2], acc[i][3]);
        float4 v1 = make_float4(acc[i][4], acc[i][5], acc[i][6], acc[i][7]);
        *reinterpret_cast<float4*>(&Cout[(size_t)(x0 + trow + i) * Y_ + y0 + tcol])     = v0;
        *reinterpret_cast<float4*>(&Cout[(size_t)(x0 + trow + i) * Y_ + y0 + tcol + 4]) = v1;
    }
}

// ---------------------------------------------------------------------------
// Final: out[b, c>=1, x, y] /= clip(out[b, 0, x, y], 1e-6, 1e5)
// ---------------------------------------------------------------------------
__global__ void divide_kernel(float* __restrict__ out) {
    int idx = blockIdx.x * blockDim.x + threadIdx.x;
    const int TOT = B_ * X_ * Y_;
    if (idx >= TOT) return;
    int b  = idx / (X_ * Y_);
    int xy = idx % (X_ * Y_);
    float* base = out + (size_t)b * CP1 * X_ * Y_ + xy;
    float d = base[0];
    d = fminf(fmaxf(d, 1e-6f), 1e5f);
    float invd = 1.0f / d;   // one accurate divide, reused
#pragma unroll 4
    for (int c = 1; c < CP1; c++) {
        base[(size_t)c * X_ * Y_] *= invd;
    }
}

// ---------------------------------------------------------------------------
extern "C" void kernel_launch(void* const* d_in, const int* in_sizes, int n_in,
                              void* d_out, int out_size) {
    const float* xin_lon  = (const float*)d_in[0];  // [B, W]
    const float* xin_lat  = (const float*)d_in[1];  // [B, H]
    const float* wt       = (const float*)d_in[2];  // [B, C, W, H]
    const float* xout_lon = (const float*)d_in[3];  // [B, X]
    const float* xout_lat = (const float*)d_in[4];  // [B, Y]
    const float* init_ls  = (const float*)d_in[5];  // [1]
    float* out = (float*)d_out;                     // [B, C+1, X, Y]

    (void)in_sizes; (void)n_in; (void)out_size;

    const int nrbf = B_ * X_ * W_ + B_ * H_ * Y_;
    rbf_kernel<<<(nrbf + 255) / 256, 256>>>(xin_lon, xin_lat, xout_lon, xout_lat, init_ls);

    // Stage A: grid (N tiles, M tiles, B*(C+1))
    gemm_stageA<<<dim3(H_ / BN, X_ / BM, B_ * CP1), NTHREADS>>>(wt);

    // Stage B
    gemm_stageB<<<dim3(Y_ / BN, X_ / BM, B_ * CP1), NTHREADS>>>(out);

    // Density division
    divide_kernel<<<(B_ * X_ * Y_ + 255) / 256, 256>>>(out);
}

// round 3
// speedup vs baseline: 2.5387x; 2.5387x over previous
#include <cuda_runtime.h>
#include <cstdint>
#include <math.h>

// Problem dims (fixed)
#define B_   2
#define C_   32
#define CP1  33
#define W_   256
#define H_   256
#define X_   512
#define Y_   512
#define XY   (X_ * Y_)

// GEMM tiling
#define BM 128
#define BN 128
#define BK 16
#define NTH 256
#define AS_STRIDE 20    // [m][k] padded: conflict-free A-frag LDS
#define BS_STRIDE 136   // [k][n] padded: conflict-free B-frag LDS

// Scratch (static __device__, no allocation in kernel_launch)
__device__ __align__(128) float g_wlon[B_ * X_ * W_];                  // [b][x][w]  (tf32-rounded)
__device__ __align__(128) float g_wlat[B_ * H_ * Y_];                  // [b][h][y]  (tf32-rounded)
__device__ __align__(128) float g_wtf[(size_t)B_ * CP1 * W_ * H_];     // wt_full   (tf32-rounded)
__device__ __align__(128) float g_tmp[(size_t)B_ * CP1 * X_ * H_];     // stage-A out (tf32-rounded)
__device__ __align__(128) float g_invd[B_ * XY];                       // 1/clip(density)

// ---------------------------------------------------------------------------
// tf32 helpers
// ---------------------------------------------------------------------------
__device__ __forceinline__ uint32_t f2tf32(float f) {
    uint32_t u;
    asm("cvt.rna.tf32.f32 %0, %1;" : "=r"(u) : "f"(f));
    return u;
}
__device__ __forceinline__ float round_tf32(float f) {
    return __uint_as_float(f2tf32(f));
}

__device__ __forceinline__ void mma_tf32(float* d, const uint32_t* a,
                                         uint32_t b0, uint32_t b1) {
    asm volatile(
        "mma.sync.aligned.m16n8k8.row.col.f32.tf32.tf32.f32 "
        "{%0,%1,%2,%3}, {%4,%5,%6,%7}, {%8,%9}, {%0,%1,%2,%3};\n"
        : "+f"(d[0]), "+f"(d[1]), "+f"(d[2]), "+f"(d[3])
        : "r"(a[0]), "r"(a[1]), "r"(a[2]), "r"(a[3]), "r"(b0), "r"(b1));
}

__device__ __forceinline__ void cpasync16(void* dst, const void* src) {
    uint32_t sa = (uint32_t)__cvta_generic_to_shared(dst);
    asm volatile("cp.async.cg.shared.global [%0], [%1], 16;" :: "r"(sa), "l"(src));
}

// ---------------------------------------------------------------------------
// RBF weights (written pre-rounded to tf32)
// ---------------------------------------------------------------------------
__global__ void rbf_kernel(const float* __restrict__ xin_lon,
                           const float* __restrict__ xin_lat,
                           const float* __restrict__ xout_lon,
                           const float* __restrict__ xout_lat,
                           const float* __restrict__ init_ls) {
    const float ls  = init_ls[0];
    const float inv = -0.5f / (ls * ls);
    const int NLON = B_ * X_ * W_;
    const int NLAT = B_ * H_ * Y_;
    int idx = blockIdx.x * blockDim.x + threadIdx.x;
    if (idx < NLON) {
        int w = idx % W_;
        int x = (idx / W_) % X_;
        int b = idx / (W_ * X_);
        float d = xin_lon[b * W_ + w] - xout_lon[b * X_ + x];
        g_wlon[idx] = round_tf32(__expf(inv * d * d));
    } else if (idx < NLON + NLAT) {
        int i = idx - NLON;
        int y = i % Y_;
        int h = (i / Y_) % H_;
        int b = i / (Y_ * H_);
        float d = xin_lat[b * H_ + h] - xout_lat[b * Y_ + y];
        g_wlat[i] = round_tf32(__expf(inv * d * d));
    }
}

// ---------------------------------------------------------------------------
// Materialize wt_full (pre-rounded to tf32):
//   channel 0 = density(isnan -> 0 else 1), c>=1 = nan_to_num
// ---------------------------------------------------------------------------
__global__ void prep_wt(const float* __restrict__ wt) {
    const int PER_C4 = W_ * H_ / 4;
    int idx = blockIdx.x * blockDim.x + threadIdx.x;
    if (idx >= B_ * CP1 * PER_C4) return;
    int bc = idx / PER_C4;
    int r  = idx % PER_C4;
    int b  = bc / CP1;
    int c  = bc % CP1;
    const float4* src = reinterpret_cast<const float4*>(wt) +
                        ((size_t)b * C_ + (c == 0 ? 0 : (c - 1))) * PER_C4 + r;
    float4 v = *src;
    if (c == 0) {
        v.x = (v.x != v.x) ? 0.0f : 1.0f;
        v.y = (v.y != v.y) ? 0.0f : 1.0f;
        v.z = (v.z != v.z) ? 0.0f : 1.0f;
        v.w = (v.w != v.w) ? 0.0f : 1.0f;
    } else {
        v.x = (v.x != v.x) ? 0.0f : round_tf32(v.x);
        v.y = (v.y != v.y) ? 0.0f : round_tf32(v.y);
        v.z = (v.z != v.z) ? 0.0f : round_tf32(v.z);
        v.w = (v.w != v.w) ? 0.0f : round_tf32(v.w);
    }
    reinterpret_cast<float4*>(g_wtf)[idx] = v;
}

// ---------------------------------------------------------------------------
// tf32 MMA GEMM: C[M=512, N] = A[512, 256] * B[256, N]   (all row-major)
// All operands are pre-rounded to tf32 — inner loop loads bits directly.
// KIND 0: stage A  (A=g_wlon[b], B=g_wtf[bc], C=g_tmp[bc], N=256; C pre-rounded)
// KIND 1: stage B density (c=0): C=out plane, epilogue writes g_invd, N=512
// KIND 2: stage B rest (c>=1): epilogue multiplies by g_invd, N=512
// ---------------------------------------------------------------------------
template <int KIND>
__global__ __launch_bounds__(NTH, 2)
void mma_gemm(float* __restrict__ out) {
    constexpr int N = (KIND == 0) ? H_ : Y_;
    constexpr int K = 256;
    constexpr int KT = K / BK;

    const float* Ag;
    const float* Bg;
    float* Cg;
    int b;
    if (KIND == 0) {
        int bc = blockIdx.z;
        b = bc / CP1;
        Ag = g_wlon + (size_t)b * X_ * W_;
        Bg = g_wtf + (size_t)bc * W_ * H_;
        Cg = g_tmp + (size_t)bc * X_ * H_;
    } else if (KIND == 1) {
        b = blockIdx.z;
        Ag = g_tmp + (size_t)(b * CP1) * X_ * H_;
        Bg = g_wlat + (size_t)b * H_ * Y_;
        Cg = out + (size_t)(b * CP1) * XY;
    } else {
        int z = blockIdx.z;
        b = z >> 5;
        int c = (z & 31) + 1;
        Ag = g_tmp + (size_t)(b * CP1 + c) * X_ * H_;
        Bg = g_wlat + (size_t)b * H_ * Y_;
        Cg = out + (size_t)(b * CP1 + c) * XY;
    }

    const int x0 = blockIdx.y * BM;
    const int n0 = blockIdx.x * BN;
    Ag += (size_t)x0 * K;
    Bg += n0;

    __shared__ __align__(16) float As[2 * BM * AS_STRIDE];  // [buf][m][k]
    __shared__ __align__(16) float Bs[2 * BK * BS_STRIDE];  // [buf][k][n]

    const int tid  = threadIdx.x;
    const int lane = tid & 31;
    const int wid  = tid >> 5;
    const int wr   = wid >> 2;      // warp m: 0..1 (x64 rows)
    const int wc   = wid & 3;       // warp n: 0..3 (x32 cols)
    const int lr   = lane >> 2;
    const int lc   = lane & 3;

    float acc[4][4][4];
#pragma unroll
    for (int i = 0; i < 4; i++)
#pragma unroll
        for (int j = 0; j < 4; j++)
#pragma unroll
            for (int r = 0; r < 4; r++) acc[i][j][r] = 0.0f;

    const int ar0 = tid >> 2,           akc0 = (tid & 3) * 4;
    const int ar1 = (tid + 256) >> 2,   akc1 = ((tid + 256) & 3) * 4;
    const int bk0 = tid >> 5,           bnc0 = (tid & 31) * 4;
    const int bk1 = (tid + 256) >> 5,   bnc1 = ((tid + 256) & 31) * 4;

    auto load_tiles = [&](int buf, int kt) {
        float* Asb = As + buf * (BM * AS_STRIDE);
        float* Bsb = Bs + buf * (BK * BS_STRIDE);
        cpasync16(&Asb[ar0 * AS_STRIDE + akc0], Ag + (size_t)ar0 * K + kt * BK + akc0);
        cpasync16(&Asb[ar1 * AS_STRIDE + akc1], Ag + (size_t)ar1 * K + kt * BK + akc1);
        cpasync16(&Bsb[bk0 * BS_STRIDE + bnc0], Bg + (size_t)(kt * BK + bk0) * N + bnc0);
        cpasync16(&Bsb[bk1 * BS_STRIDE + bnc1], Bg + (size_t)(kt * BK + bk1) * N + bnc1);
        asm volatile("cp.async.commit_group;");
    };

    load_tiles(0, 0);

    int buf = 0;
    for (int kt = 0; kt < KT; kt++) {
        asm volatile("cp.async.wait_group 0;");
        __syncthreads();
        if (kt + 1 < KT) load_tiles(buf ^ 1, kt + 1);

        const float* Asb = As + buf * (BM * AS_STRIDE);
        const float* Bsb = Bs + buf * (BK * BS_STRIDE);

#pragma unroll
        for (int ks = 0; ks < BK; ks += 8) {
            uint32_t af[4][4];
#pragma unroll
            for (int mi = 0; mi < 4; mi++) {
                const float* Ap = &Asb[(wr * 64 + mi * 16 + lr) * AS_STRIDE + ks + lc];
                af[mi][0] = __float_as_uint(Ap[0]);
                af[mi][1] = __float_as_uint(Ap[8 * AS_STRIDE]);
                af[mi][2] = __float_as_uint(Ap[4]);
                af[mi][3] = __float_as_uint(Ap[8 * AS_STRIDE + 4]);
            }
#pragma unroll
            for (int ni = 0; ni < 4; ni++) {
                const float* Bp = &Bsb[(ks + lc) * BS_STRIDE + wc * 32 + ni * 8 + lr];
                uint32_t b0 = __float_as_uint(Bp[0]);
                uint32_t b1 = __float_as_uint(Bp[4 * BS_STRIDE]);
#pragma unroll
                for (int mi = 0; mi < 4; mi++)
                    mma_tf32(acc[mi][ni], af[mi], b0, b1);
            }
        }
        buf ^= 1;
    }

    // Epilogue
#pragma unroll
    for (int mi = 0; mi < 4; mi++) {
#pragma unroll
        for (int ni = 0; ni < 4; ni++) {
            int r0  = x0 + wr * 64 + mi * 16 + lr;
            int col = n0 + wc * 32 + ni * 8 + 2 * lc;
            float d0 = acc[mi][ni][0], d1 = acc[mi][ni][1];
            float d2 = acc[mi][ni][2], d3 = acc[mi][ni][3];

            if (KIND == 0) {
                // pre-round for stage-B consumption (equivalent to in-loop cvt)
                d0 = round_tf32(d0); d1 = round_tf32(d1);
                d2 = round_tf32(d2); d3 = round_tf32(d3);
            }

            if (KIND == 2) {
                float2 i0 = *reinterpret_cast<const float2*>(
                    &g_invd[(size_t)b * XY + (size_t)r0 * Y_ + col]);
                float2 i1 = *reinterpret_cast<const float2*>(
                    &g_invd[(size_t)b * XY + (size_t)(r0 + 8) * Y_ + col]);
                d0 *= i0.x; d1 *= i0.y; d2 *= i1.x; d3 *= i1.y;
            }

            *reinterpret_cast<float2*>(&Cg[(size_t)r0 * N + col]) = make_float2(d0, d1);
            *reinterpret_cast<float2*>(&Cg[(size_t)(r0 + 8) * N + col]) = make_float2(d2, d3);

            if (KIND == 1) {
                float c0 = fminf(fmaxf(d0, 1e-6f), 1e5f);
                float c1 = fminf(fmaxf(d1, 1e-6f), 1e5f);
                float c2 = fminf(fmaxf(d2, 1e-6f), 1e5f);
                float c3 = fminf(fmaxf(d3, 1e-6f), 1e5f);
                float* ip = g_invd + (size_t)b * XY;
                *reinterpret_cast<float2*>(&ip[(size_t)r0 * Y_ + col]) =
                    make_float2(1.0f / c0, 1.0f / c1);
                *reinterpret_cast<float2*>(&ip[(size_t)(r0 + 8) * Y_ + col]) =
                    make_float2(1.0f / c2, 1.0f / c3);
            }
        }
    }
}

// ---------------------------------------------------------------------------
extern "C" void kernel_launch(void* const* d_in, const int* in_sizes, int n_in,
                              void* d_out, int out_size) {
    const float* xin_lon  = (const float*)d_in[0];
    const float* xin_lat  = (const float*)d_in[1];
    const float* wt       = (const float*)d_in[2];
    const float* xout_lon = (const float*)d_in[3];
    const float* xout_lat = (const float*)d_in[4];
    const float* init_ls  = (const float*)d_in[5];
    float* out = (float*)d_out;
    (void)in_sizes; (void)n_in; (void)out_size;

    const int nrbf = B_ * X_ * W_ + B_ * H_ * Y_;
    rbf_kernel<<<(nrbf + 255) / 256, 256>>>(xin_lon, xin_lat, xout_lon, xout_lat, init_ls);

    const int nprep = B_ * CP1 * W_ * H_ / 4;
    prep_wt<<<(nprep + 255) / 256, 256>>>(wt);

    // Stage A: 66 batched GEMMs, M=512 N=256 K=256
    mma_gemm<0><<<dim3(H_ / BN, X_ / BM, B_ * CP1), NTH>>>(out);

    // Stage B density channel (c=0): also produces reciprocal plane
    mma_gemm<1><<<dim3(Y_ / BN, X_ / BM, B_), NTH>>>(out);

    // Stage B remaining 32 channels with fused division
    mma_gemm<2><<<dim3(Y_ / BN, X_ / BM, B_ * C_), NTH>>>(out);
}

// round 5
// speedup vs baseline: 3.8515x; 1.5171x over previous
#include <cuda_runtime.h>
#include <cuda_fp16.h>
#include <cstdint>
#include <math.h>

// Problem dims (fixed)
#define B_   2
#define C_   32
#define CP1  33
#define W_   256
#define H_   256
#define X_   512
#define Y_   512
#define XY   (X_ * Y_)
#define K_   256      // contraction depth for both stages

// GEMM tiling (fp16 m16n8k16)
#define BM 128
#define BN 128
#define BK 32
#define NTH 256
#define SA 40        // padded smem stride in fp16 units (conflict-free)

// Scratch (static __device__, no allocation in kernel_launch)
__device__ __align__(128) __half g_wlon[B_ * X_ * W_];                 // [b][x][w]
__device__ __align__(128) __half g_wlat[B_ * Y_ * H_];                 // [b][y][h]  (pre-transposed)
__device__ __align__(128) __half g_wtf[(size_t)B_ * CP1 * H_ * W_];    // wt_full [b][c][h][w] (transposed)
__device__ __align__(128) __half g_tmp[(size_t)B_ * CP1 * X_ * H_];    // stage-A out [b][c][x][h]
__device__ __align__(128) float  g_invd[B_ * XY];                      // 1/clip(density)

// ---------------------------------------------------------------------------
__device__ __forceinline__ void mma_f16(float* d, const uint32_t* a,
                                        uint32_t b0, uint32_t b1) {
    asm volatile(
        "mma.sync.aligned.m16n8k16.row.col.f32.f16.f16.f32 "
        "{%0,%1,%2,%3}, {%4,%5,%6,%7}, {%8,%9}, {%0,%1,%2,%3};\n"
        : "+f"(d[0]), "+f"(d[1]), "+f"(d[2]), "+f"(d[3])
        : "r"(a[0]), "r"(a[1]), "r"(a[2]), "r"(a[3]), "r"(b0), "r"(b1));
}

__device__ __forceinline__ void cpasync16(void* dst, const void* src) {
    uint32_t sa = (uint32_t)__cvta_generic_to_shared(dst);
    asm volatile("cp.async.cg.shared.global [%0], [%1], 16;" :: "r"(sa), "l"(src));
}

// ---------------------------------------------------------------------------
// RBF weights, written fp16. wlat written pre-transposed [b][y][h].
// ---------------------------------------------------------------------------
__global__ void rbf_kernel(const float* __restrict__ xin_lon,
                           const float* __restrict__ xin_lat,
                           const float* __restrict__ xout_lon,
                           const float* __restrict__ xout_lat,
                           const float* __restrict__ init_ls) {
    const float ls  = init_ls[0];
    const float inv = -0.5f / (ls * ls);
    const int NLON = B_ * X_ * W_;
    const int NLAT = B_ * Y_ * H_;
    int idx = blockIdx.x * blockDim.x + threadIdx.x;
    if (idx < NLON) {
        int w = idx % W_;
        int x = (idx / W_) % X_;
        int b = idx / (W_ * X_);
        float d = xin_lon[b * W_ + w] - xout_lon[b * X_ + x];
        g_wlon[idx] = __float2half_rn(__expf(inv * d * d));
    } else if (idx < NLON + NLAT) {
        int i = idx - NLON;
        int h = i % H_;
        int y = (i / H_) % Y_;
        int b = i / (H_ * Y_);
        float d = xin_lat[b * H_ + h] - xout_lat[b * Y_ + y];
        g_wlat[i] = __float2half_rn(__expf(inv * d * d));
    }
}

// ---------------------------------------------------------------------------
// wt_full: transpose [w][h] -> [h][w] per channel, NaN/density fix, fp32->fp16
// ---------------------------------------------------------------------------
__global__ void prep_wt_t(const float* __restrict__ wt) {
    __shared__ __half t[32][33];
    const int bc = blockIdx.z;
    const int b  = bc / CP1;
    const int c  = bc % CP1;
    const int w0 = blockIdx.x * 32;
    const int h0 = blockIdx.y * 32;
    const int tx = threadIdx.x;       // 0..31
    const int ty = threadIdx.y;       // 0..7
    const float* src = wt + ((size_t)b * C_ + (c == 0 ? 0 : (c - 1))) * W_ * H_;
    __half* dst = g_wtf + (size_t)bc * H_ * W_;

#pragma unroll
    for (int j = 0; j < 4; j++) {
        int w = w0 + ty + j * 8;
        float v = src[(size_t)w * H_ + h0 + tx];
        float r;
        if (c == 0) r = (v != v) ? 0.0f : 1.0f;
        else        r = (v != v) ? 0.0f : v;
        t[ty + j * 8][tx] = __float2half_rn(r);
    }
    __syncthreads();
#pragma unroll
    for (int j = 0; j < 4; j++) {
        int h = h0 + ty + j * 8;
        dst[(size_t)h * W_ + w0 + tx] = t[tx][ty + j * 8];
    }
}

// ---------------------------------------------------------------------------
// fp16 MMA GEMM, 128x128 tiles. A: [M][K] fp16. B: [N][K] fp16 (pre-transposed).
// KIND 0: stage A  (A=g_wlon[b], B=g_wtf[bc], C=g_tmp fp16, N=256)
// KIND 2: stage B c>=1 (A=g_tmp[bc], B=g_wlat[b], C=out fp32 * invd, N=512)
// ---------------------------------------------------------------------------
template <int KIND>
__global__ __launch_bounds__(NTH, 2)
void mma_gemm(float* __restrict__ out) {
    constexpr int N = (KIND == 0) ? H_ : Y_;
    constexpr int KT = K_ / BK;

    const __half* Ag;
    const __half* Bg;
    int b;
    __half* Ch = nullptr;
    float*  Cf = nullptr;
    if (KIND == 0) {
        int bc = blockIdx.z;
        b = bc / CP1;
        Ag = g_wlon + (size_t)b * X_ * W_;
        Bg = g_wtf + (size_t)bc * H_ * W_;
        Ch = g_tmp + (size_t)bc * X_ * H_;
    } else {
        int z = blockIdx.z;
        b = z >> 5;
        int c = (z & 31) + 1;
        Ag = g_tmp + (size_t)(b * CP1 + c) * X_ * H_;
        Bg = g_wlat + (size_t)b * Y_ * H_;
        Cf = out + (size_t)(b * CP1 + c) * XY;
    }

    const int x0 = blockIdx.y * BM;
    const int n0 = blockIdx.x * BN;
    Ag += (size_t)x0 * K_;
    Bg += (size_t)n0 * K_;

    __shared__ __align__(16) __half As[2 * BM * SA];
    __shared__ __align__(16) __half Bs[2 * BN * SA];

    const int tid  = threadIdx.x;
    const int lane = tid & 31;
    const int wid  = tid >> 5;
    const int wr   = wid >> 2;      // 0..1 : 64-row warp tile
    const int wc   = wid & 3;       // 0..3 : 32-col warp tile
    const int lr   = lane >> 2;
    const int lc   = lane & 3;

    float acc[4][4][4];
#pragma unroll
    for (int i = 0; i < 4; i++)
#pragma unroll
        for (int j = 0; j < 4; j++)
#pragma unroll
            for (int r = 0; r < 4; r++) acc[i][j][r] = 0.0f;

    auto load_tiles = [&](int buf, int kt) {
        __half* Asb = As + buf * (BM * SA);
        __half* Bsb = Bs + buf * (BN * SA);
#pragma unroll
        for (int j = 0; j < 2; j++) {
            int i = tid + j * NTH;            // 0..511
            int row = i >> 2;
            int c8  = (i & 3) * 8;            // fp16 element offset
            cpasync16(&Asb[row * SA + c8], Ag + (size_t)row * K_ + kt * BK + c8);
            cpasync16(&Bsb[row * SA + c8], Bg + (size_t)row * K_ + kt * BK + c8);
        }
        asm volatile("cp.async.commit_group;");
    };

    load_tiles(0, 0);

    int buf = 0;
    for (int kt = 0; kt < KT; kt++) {
        asm volatile("cp.async.wait_group 0;");
        __syncthreads();
        if (kt + 1 < KT) load_tiles(buf ^ 1, kt + 1);

        const __half* Asb = As + buf * (BM * SA);
        const __half* Bsb = Bs + buf * (BN * SA);

#pragma unroll
        for (int ks = 0; ks < BK; ks += 16) {
            uint32_t af[4][4];
#pragma unroll
            for (int mi = 0; mi < 4; mi++) {
                const __half* Ap = &Asb[(wr * 64 + mi * 16 + lr) * SA + ks + 2 * lc];
                af[mi][0] = *reinterpret_cast<const uint32_t*>(Ap);
                af[mi][1] = *reinterpret_cast<const uint32_t*>(Ap + 8 * SA);
                af[mi][2] = *reinterpret_cast<const uint32_t*>(Ap + 8);
                af[mi][3] = *reinterpret_cast<const uint32_t*>(Ap + 8 * SA + 8);
            }
#pragma unroll
            for (int ni = 0; ni < 4; ni++) {
                const __half* Bp = &Bsb[(wc * 32 + ni * 8 + lr) * SA + ks + 2 * lc];
                uint32_t b0 = *reinterpret_cast<const uint32_t*>(Bp);
                uint32_t b1 = *reinterpret_cast<const uint32_t*>(Bp + 8);
#pragma unroll
                for (int mi = 0; mi < 4; mi++)
                    mma_f16(acc[mi][ni], af[mi], b0, b1);
            }
        }
        buf ^= 1;
    }

    // Epilogue
#pragma unroll
    for (int mi = 0; mi < 4; mi++) {
#pragma unroll
        for (int ni = 0; ni < 4; ni++) {
            int r0  = x0 + wr * 64 + mi * 16 + lr;
            int col = n0 + wc * 32 + ni * 8 + 2 * lc;
            float d0 = acc[mi][ni][0], d1 = acc[mi][ni][1];
            float d2 = acc[mi][ni][2], d3 = acc[mi][ni][3];

            if (KIND == 0) {
                *reinterpret_cast<__half2*>(&Ch[(size_t)r0 * N + col]) =
                    __floats2half2_rn(d0, d1);
                *reinterpret_cast<__half2*>(&Ch[(size_t)(r0 + 8) * N + col]) =
                    __floats2half2_rn(d2, d3);
            } else {
                float2 i0 = *reinterpret_cast<const float2*>(
                    &g_invd[(size_t)b * XY + (size_t)r0 * Y_ + col]);
                float2 i1 = *reinterpret_cast<const float2*>(
                    &g_invd[(size_t)b * XY + (size_t)(r0 + 8) * Y_ + col]);
                *reinterpret_cast<float2*>(&Cf[(size_t)r0 * N + col]) =
                    make_float2(d0 * i0.x, d1 * i0.y);
                *reinterpret_cast<float2*>(&Cf[(size_t)(r0 + 8) * N + col]) =
                    make_float2(d2 * i1.x, d3 * i1.y);
            }
        }
    }
}

// ---------------------------------------------------------------------------
// Density stage-B: 64x64 tiles, 128 threads, grid (8,8,2)=128 CTAs.
// C = tmp[b][0] (fp16 [X][H]) x wlat[b] ([Y][H]) -> out plane 0 + g_invd.
// ---------------------------------------------------------------------------
__global__ __launch_bounds__(128, 4)
void dens_gemm(float* __restrict__ out) {
    constexpr int TBM = 64, TBN = 64;
    constexpr int KT = K_ / BK;

    const int b  = blockIdx.z;
    const __half* Ag = g_tmp + (size_t)(b * CP1) * X_ * H_;
    const __half* Bg = g_wlat + (size_t)b * Y_ * H_;
    float* Cf = out + (size_t)(b * CP1) * XY;
    float* ip = g_invd + (size_t)b * XY;

    const int x0 = blockIdx.y * TBM;
    const int n0 = blockIdx.x * TBN;
    Ag += (size_t)x0 * K_;
    Bg += (size_t)n0 * K_;

    __shared__ __align__(16) __half As[2 * TBM * SA];
    __shared__ __align__(16) __half Bs[2 * TBN * SA];

    const int tid  = threadIdx.x;
    const int lane = tid & 31;
    const int wid  = tid >> 5;      // 0..3
    const int wr   = wid >> 1;      // 0..1 : 32-row warp tile
    const int wc   = wid & 1;       // 0..1 : 32-col warp tile
    const int lr   = lane >> 2;
    const int lc   = lane & 3;

    float acc[2][4][4];
#pragma unroll
    for (int i = 0; i < 2; i++)
#pragma unroll
        for (int j = 0; j < 4; j++)
#pragma unroll
            for (int r = 0; r < 4; r++) acc[i][j][r] = 0.0f;

    auto load_tiles = [&](int buf, int kt) {
        __half* Asb = As + buf * (TBM * SA);
        __half* Bsb = Bs + buf * (TBN * SA);
#pragma unroll
        for (int j = 0; j < 2; j++) {
            int i = tid + j * 128;            // 0..255
            int row = i >> 2;
            int c8  = (i & 3) * 8;
            cpasync16(&Asb[row * SA + c8], Ag + (size_t)row * K_ + kt * BK + c8);
            cpasync16(&Bsb[row * SA + c8], Bg + (size_t)row * K_ + kt * BK + c8);
        }
        asm volatile("cp.async.commit_group;");
    };

    load_tiles(0, 0);

    int buf = 0;
    for (int kt = 0; kt < KT; kt++) {
        asm volatile("cp.async.wait_group 0;");
        __syncthreads();
        if (kt + 1 < KT) load_tiles(buf ^ 1, kt + 1);

        const __half* Asb = As + buf * (TBM * SA);
        const __half* Bsb = Bs + buf * (TBN * SA);

#pragma unroll
        for (int ks = 0; ks < BK; ks += 16) {
            uint32_t af[2][4];
#pragma unroll
            for (int mi = 0; mi < 2; mi++) {
                const __half* Ap = &Asb[(wr * 32 + mi * 16 + lr) * SA + ks + 2 * lc];
                af[mi][0] = *reinterpret_cast<const uint32_t*>(Ap);
                af[mi][1] = *reinterpret_cast<const uint32_t*>(Ap + 8 * SA);
                af[mi][2] = *reinterpret_cast<const uint32_t*>(Ap + 8);
                af[mi][3] = *reinterpret_cast<const uint32_t*>(Ap + 8 * SA + 8);
            }
#pragma unroll
            for (int ni = 0; ni < 4; ni++) {
                const __half* Bp = &Bsb[(wc * 32 + ni * 8 + lr) * SA + ks + 2 * lc];
                uint32_t b0 = *reinterpret_cast<const uint32_t*>(Bp);
                uint32_t b1 = *reinterpret_cast<const uint32_t*>(Bp + 8);
#pragma unroll
                for (int mi = 0; mi < 2; mi++)
                    mma_f16(acc[mi][ni], af[mi], b0, b1);
            }
        }
        buf ^= 1;
    }

#pragma unroll
    for (int mi = 0; mi < 2; mi++) {
#pragma unroll
        for (int ni = 0; ni < 4; ni++) {
            int r0  = x0 + wr * 32 + mi * 16 + lr;
            int col = n0 + wc * 32 + ni * 8 + 2 * lc;
            float d0 = acc[mi][ni][0], d1 = acc[mi][ni][1];
            float d2 = acc[mi][ni][2], d3 = acc[mi][ni][3];
            *reinterpret_cast<float2*>(&Cf[(size_t)r0 * Y_ + col]) = make_float2(d0, d1);
            *reinterpret_cast<float2*>(&Cf[(size_t)(r0 + 8) * Y_ + col]) = make_float2(d2, d3);
            float c0 = fminf(fmaxf(d0, 1e-6f), 1e5f);
            float c1 = fminf(fmaxf(d1, 1e-6f), 1e5f);
            float c2 = fminf(fmaxf(d2, 1e-6f), 1e5f);
            float c3 = fminf(fmaxf(d3, 1e-6f), 1e5f);
            *reinterpret_cast<float2*>(&ip[(size_t)r0 * Y_ + col]) =
                make_float2(1.0f / c0, 1.0f / c1);
            *reinterpret_cast<float2*>(&ip[(size_t)(r0 + 8) * Y_ + col]) =
                make_float2(1.0f / c2, 1.0f / c3);
        }
    }
}

// ---------------------------------------------------------------------------
extern "C" void kernel_launch(void* const* d_in, const int* in_sizes, int n_in,
                              void* d_out, int out_size) {
    const float* xin_lon  = (const float*)d_in[0];
    const float* xin_lat  = (const float*)d_in[1];
    const float* wt       = (const float*)d_in[2];
    const float* xout_lon = (const float*)d_in[3];
    const float* xout_lat = (const float*)d_in[4];
    const float* init_ls  = (const float*)d_in[5];
    float* out = (float*)d_out;
    (void)in_sizes; (void)n_in; (void)out_size;

    const int nrbf = B_ * X_ * W_ + B_ * Y_ * H_;
    rbf_kernel<<<(nrbf + 255) / 256, 256>>>(xin_lon, xin_lat, xout_lon, xout_lat, init_ls);

    // wt_full transpose+fix: per-channel 256x256, 32x32 tiles
    prep_wt_t<<<dim3(W_ / 32, H_ / 32, B_ * CP1), dim3(32, 8)>>>(wt);

    // Stage A: 66 GEMMs M=512 N=256 K=256 -> g_tmp (fp16)
    mma_gemm<0><<<dim3(H_ / BN, X_ / BM, B_ * CP1), NTH>>>(out);

    // Density stage-B: 64x64 tiles, writes out plane0 + g_invd
    dens_gemm<<<dim3(Y_ / 64, X_ / 64, B_), 128>>>(out);

    // Stage B remaining 32 channels, fused divide
    mma_gemm<2><<<dim3(Y_ / BN, X_ / BM, B_ * C_), NTH>>>(out);
}

// round 6
// speedup vs baseline: 4.2476x; 1.1029x over previous
#include <cuda_runtime.h>
#include <cuda_fp16.h>
#include <cstdint>
#include <math.h>

// Problem dims (fixed)
#define B_   2
#define C_   32
#define CP1  33
#define W_   256
#define H_   256
#define X_   512
#define Y_   512
#define XY   (X_ * Y_)
#define K_   256      // contraction depth for both stages

// GEMM tiling (fp16 m16n8k16)
#define BM 128
#define BN 128
#define BK 32
#define NTH 256
#define SA 40        // padded smem stride in fp16 units (conflict-free)

// Scratch (static __device__, no allocation in kernel_launch)
__device__ __align__(128) __half g_wlon[B_ * X_ * W_];                 // [b][x][w]
__device__ __align__(128) __half g_wlat[B_ * Y_ * H_];                 // [b][y][h]  (pre-transposed)
__device__ __align__(128) __half g_wtf[(size_t)B_ * CP1 * H_ * W_];    // wt_full [b][c][h][w] (transposed)
__device__ __align__(128) __half g_tmp[(size_t)B_ * CP1 * X_ * H_];    // stage-A out [b][c][x][h]
__device__ __align__(128) float  g_invd[B_ * XY];                      // 1/clip(density)

// ---------------------------------------------------------------------------
__device__ __forceinline__ void mma_f16(float* d, const uint32_t* a,
                                        uint32_t b0, uint32_t b1) {
    asm volatile(
        "mma.sync.aligned.m16n8k16.row.col.f32.f16.f16.f32 "
        "{%0,%1,%2,%3}, {%4,%5,%6,%7}, {%8,%9}, {%0,%1,%2,%3};\n"
        : "+f"(d[0]), "+f"(d[1]), "+f"(d[2]), "+f"(d[3])
        : "r"(a[0]), "r"(a[1]), "r"(a[2]), "r"(a[3]), "r"(b0), "r"(b1));
}

__device__ __forceinline__ void cpasync16(void* dst, const void* src) {
    uint32_t sa = (uint32_t)__cvta_generic_to_shared(dst);
    asm volatile("cp.async.cg.shared.global [%0], [%1], 16;" :: "r"(sa), "l"(src));
}

__device__ __forceinline__ void ldsm_x4(uint32_t& r0, uint32_t& r1,
                                        uint32_t& r2, uint32_t& r3, uint32_t addr) {
    asm volatile("ldmatrix.sync.aligned.m8n8.x4.shared.b16 {%0,%1,%2,%3}, [%4];"
                 : "=r"(r0), "=r"(r1), "=r"(r2), "=r"(r3) : "r"(addr));
}

// ---------------------------------------------------------------------------
// RBF weights, written fp16. wlat written pre-transposed [b][y][h].
// ---------------------------------------------------------------------------
__global__ void rbf_kernel(const float* __restrict__ xin_lon,
                           const float* __restrict__ xin_lat,
                           const float* __restrict__ xout_lon,
                           const float* __restrict__ xout_lat,
                           const float* __restrict__ init_ls) {
    const float ls  = init_ls[0];
    const float inv = -0.5f / (ls * ls);
    const int NLON = B_ * X_ * W_;
    const int NLAT = B_ * Y_ * H_;
    int idx = blockIdx.x * blockDim.x + threadIdx.x;
    if (idx < NLON) {
        int w = idx % W_;
        int x = (idx / W_) % X_;
        int b = idx / (W_ * X_);
        float d = xin_lon[b * W_ + w] - xout_lon[b * X_ + x];
        g_wlon[idx] = __float2half_rn(__expf(inv * d * d));
    } else if (idx < NLON + NLAT) {
        int i = idx - NLON;
        int h = i % H_;
        int y = (i / H_) % Y_;
        int b = i / (H_ * Y_);
        float d = xin_lat[b * H_ + h] - xout_lat[b * Y_ + y];
        g_wlat[i] = __float2half_rn(__expf(inv * d * d));
    }
}

// ---------------------------------------------------------------------------
// wt_full: transpose [w][h] -> [h][w] per channel, NaN/density fix, fp32->fp16
// ---------------------------------------------------------------------------
__global__ void prep_wt_t(const float* __restrict__ wt) {
    __shared__ __half t[32][33];
    const int bc = blockIdx.z;
    const int b  = bc / CP1;
    const int c  = bc % CP1;
    const int w0 = blockIdx.x * 32;
    const int h0 = blockIdx.y * 32;
    const int tx = threadIdx.x;       // 0..31
    const int ty = threadIdx.y;       // 0..7
    const float* src = wt + ((size_t)b * C_ + (c == 0 ? 0 : (c - 1))) * W_ * H_;
    __half* dst = g_wtf + (size_t)bc * H_ * W_;

#pragma unroll
    for (int j = 0; j < 4; j++) {
        int w = w0 + ty + j * 8;
        float v = src[(size_t)w * H_ + h0 + tx];
        float r;
        if (c == 0) r = (v != v) ? 0.0f : 1.0f;
        else        r = (v != v) ? 0.0f : v;
        t[ty + j * 8][tx] = __float2half_rn(r);
    }
    __syncthreads();
#pragma unroll
    for (int j = 0; j < 4; j++) {
        int h = h0 + ty + j * 8;
        dst[(size_t)h * W_ + w0 + tx] = t[tx][ty + j * 8];
    }
}

// ---------------------------------------------------------------------------
// fp16 MMA GEMM, 128x128 tiles, ldmatrix fragment loads.
// A: [M][K] fp16. B: [N][K] fp16 (pre-transposed).
// KIND 0: stage A  (A=g_wlon[b], B=g_wtf[bc], C=g_tmp fp16, N=256)
// KIND 2: stage B c>=1 (A=g_tmp[bc], B=g_wlat[b], C=out fp32 * invd, N=512)
// ---------------------------------------------------------------------------
template <int KIND>
__global__ __launch_bounds__(NTH, 2)
void mma_gemm(float* __restrict__ out) {
    constexpr int N = (KIND == 0) ? H_ : Y_;
    constexpr int KT = K_ / BK;

    const __half* Ag;
    const __half* Bg;
    int b;
    __half* Ch = nullptr;
    float*  Cf = nullptr;
    if (KIND == 0) {
        int bc = blockIdx.z;
        b = bc / CP1;
        Ag = g_wlon + (size_t)b * X_ * W_;
        Bg = g_wtf + (size_t)bc * H_ * W_;
        Ch = g_tmp + (size_t)bc * X_ * H_;
    } else {
        int z = blockIdx.z;
        b = z >> 5;
        int c = (z & 31) + 1;
        Ag = g_tmp + (size_t)(b * CP1 + c) * X_ * H_;
        Bg = g_wlat + (size_t)b * Y_ * H_;
        Cf = out + (size_t)(b * CP1 + c) * XY;
    }

    const int x0 = blockIdx.y * BM;
    const int n0 = blockIdx.x * BN;
    Ag += (size_t)x0 * K_;
    Bg += (size_t)n0 * K_;

    __shared__ __align__(16) __half As[2 * BM * SA];
    __shared__ __align__(16) __half Bs[2 * BN * SA];

    const int tid  = threadIdx.x;
    const int lane = tid & 31;
    const int wid  = tid >> 5;
    const int wr   = wid >> 2;      // 0..1 : 64-row warp tile
    const int wc   = wid & 3;       // 0..3 : 32-col warp tile
    const int lr   = lane >> 2;
    const int lc   = lane & 3;

    const uint32_t As32 = (uint32_t)__cvta_generic_to_shared(As);
    const uint32_t Bs32 = (uint32_t)__cvta_generic_to_shared(Bs);

    // ldmatrix lane->address components
    const int laRow  = wr * 64 + (lane & 15);       // A: row within tile (per mi add mi*16)
    const int laKoff = (lane >> 4) * 8;             // A: k offset within 16-wide frag
    const int lbRow  = wc * 32 + ((lane >> 4) << 3) + (lane & 7);  // B: pair p adds p*16
    const int lbKoff = ((lane >> 3) & 1) * 8;

    float acc[4][4][4];
#pragma unroll
    for (int i = 0; i < 4; i++)
#pragma unroll
        for (int j = 0; j < 4; j++)
#pragma unroll
            for (int r = 0; r < 4; r++) acc[i][j][r] = 0.0f;

    auto load_tiles = [&](int buf, int kt) {
        __half* Asb = As + buf * (BM * SA);
        __half* Bsb = Bs + buf * (BN * SA);
#pragma unroll
        for (int j = 0; j < 2; j++) {
            int i = tid + j * NTH;            // 0..511
            int row = i >> 2;
            int c8  = (i & 3) * 8;            // fp16 element offset
            cpasync16(&Asb[row * SA + c8], Ag + (size_t)row * K_ + kt * BK + c8);
            cpasync16(&Bsb[row * SA + c8], Bg + (size_t)row * K_ + kt * BK + c8);
        }
        asm volatile("cp.async.commit_group;");
    };

    load_tiles(0, 0);

    int buf = 0;
    for (int kt = 0; kt < KT; kt++) {
        asm volatile("cp.async.wait_group 0;");
        __syncthreads();
        if (kt + 1 < KT) load_tiles(buf ^ 1, kt + 1);

        const uint32_t Aoff = As32 + buf * (BM * SA * 2);
        const uint32_t Boff = Bs32 + buf * (BN * SA * 2);

#pragma unroll
        for (int ks = 0; ks < BK; ks += 16) {
            uint32_t af[4][4];
#pragma unroll
            for (int mi = 0; mi < 4; mi++) {
                uint32_t addr = Aoff + ((laRow + mi * 16) * SA + ks + laKoff) * 2;
                ldsm_x4(af[mi][0], af[mi][1], af[mi][2], af[mi][3], addr);
            }
            uint32_t bfr[2][4];
#pragma unroll
            for (int p = 0; p < 2; p++) {
                uint32_t addr = Boff + ((lbRow + p * 16) * SA + ks + lbKoff) * 2;
                ldsm_x4(bfr[p][0], bfr[p][1], bfr[p][2], bfr[p][3], addr);
            }
#pragma unroll
            for (int ni = 0; ni < 4; ni++) {
                uint32_t b0 = bfr[ni >> 1][(ni & 1) * 2];
                uint32_t b1 = bfr[ni >> 1][(ni & 1) * 2 + 1];
#pragma unroll
                for (int mi = 0; mi < 4; mi++)
                    mma_f16(acc[mi][ni], af[mi], b0, b1);
            }
        }
        buf ^= 1;
    }

    // Epilogue
#pragma unroll
    for (int mi = 0; mi < 4; mi++) {
#pragma unroll
        for (int ni = 0; ni < 4; ni++) {
            int r0  = x0 + wr * 64 + mi * 16 + lr;
            int col = n0 + wc * 32 + ni * 8 + 2 * lc;
            float d0 = acc[mi][ni][0], d1 = acc[mi][ni][1];
            float d2 = acc[mi][ni][2], d3 = acc[mi][ni][3];

            if (KIND == 0) {
                *reinterpret_cast<__half2*>(&Ch[(size_t)r0 * N + col]) =
                    __floats2half2_rn(d0, d1);
                *reinterpret_cast<__half2*>(&Ch[(size_t)(r0 + 8) * N + col]) =
                    __floats2half2_rn(d2, d3);
            } else {
                float2 i0 = *reinterpret_cast<const float2*>(
                    &g_invd[(size_t)b * XY + (size_t)r0 * Y_ + col]);
                float2 i1 = *reinterpret_cast<const float2*>(
                    &g_invd[(size_t)b * XY + (size_t)(r0 + 8) * Y_ + col]);
                *reinterpret_cast<float2*>(&Cf[(size_t)r0 * N + col]) =
                    make_float2(d0 * i0.x, d1 * i0.y);
                *reinterpret_cast<float2*>(&Cf[(size_t)(r0 + 8) * N + col]) =
                    make_float2(d2 * i1.x, d3 * i1.y);
            }
        }
    }
}

// ---------------------------------------------------------------------------
// Density stage-B: 64x64 tiles, 256 threads (8 warps), 3-stage pipeline.
// C = tmp[b][0] (fp16 [X][H]) x wlat[b] ([Y][H]) -> out plane 0 + g_invd.
// ---------------------------------------------------------------------------
__global__ __launch_bounds__(256, 2)
void dens_gemm(float* __restrict__ out) {
    constexpr int TBM = 64, TBN = 64;
    constexpr int KT = K_ / BK;

    const int b  = blockIdx.z;
    const __half* Ag = g_tmp + (size_t)(b * CP1) * X_ * H_;
    const __half* Bg = g_wlat + (size_t)b * Y_ * H_;
    float* Cf = out + (size_t)(b * CP1) * XY;
    float* ip = g_invd + (size_t)b * XY;

    const int x0 = blockIdx.y * TBM;
    const int n0 = blockIdx.x * TBN;
    Ag += (size_t)x0 * K_;
    Bg += (size_t)n0 * K_;

    __shared__ __align__(16) __half As[3 * TBM * SA];
    __shared__ __align__(16) __half Bs[3 * TBN * SA];

    const int tid  = threadIdx.x;
    const int lane = tid & 31;
    const int wid  = tid >> 5;      // 0..7
    const int wr   = wid >> 2;      // 0..1 : 32-row warp tile
    const int wc   = wid & 3;       // 0..3 : 16-col warp tile
    const int lr   = lane >> 2;
    const int lc   = lane & 3;

    float acc[2][2][4];
#pragma unroll
    for (int i = 0; i < 2; i++)
#pragma unroll
        for (int j = 0; j < 2; j++)
#pragma unroll
            for (int r = 0; r < 4; r++) acc[i][j][r] = 0.0f;

    auto load_tiles = [&](int buf, int kt) {
        __half* Asb = As + buf * (TBM * SA);
        __half* Bsb = Bs + buf * (TBN * SA);
#pragma unroll
        for (int j = 0; j < 2; j++) {
            int i = tid + j * 256;            // 0..511 -> 256 A chunks + 256 B chunks
            int half = i >> 8;                // 0: A, 1: B
            int r = (i & 255) >> 2;
            int c8 = (i & 3) * 8;
            if (half == 0)
                cpasync16(&Asb[r * SA + c8], Ag + (size_t)r * K_ + kt * BK + c8);
            else
                cpasync16(&Bsb[r * SA + c8], Bg + (size_t)r * K_ + kt * BK + c8);
        }
        asm volatile("cp.async.commit_group;");
    };

    load_tiles(0, 0);
    load_tiles(1, 1);

    for (int kt = 0; kt < KT; kt++) {
        asm volatile("cp.async.wait_group 1;");
        __syncthreads();
        if (kt + 2 < KT) {
            load_tiles((kt + 2) % 3, kt + 2);
        } else {
            asm volatile("cp.async.commit_group;");   // keep group count stable
        }

        const __half* Asb = As + (kt % 3) * (TBM * SA);
        const __half* Bsb = Bs + (kt % 3) * (TBN * SA);

#pragma unroll
        for (int ks = 0; ks < BK; ks += 16) {
            uint32_t af[2][4];
#pragma unroll
            for (int mi = 0; mi < 2; mi++) {
                const __half* Ap = &Asb[(wr * 32 + mi * 16 + lr) * SA + ks + 2 * lc];
                af[mi][0] = *reinterpret_cast<const uint32_t*>(Ap);
                af[mi][1] = *reinterpret_cast<const uint32_t*>(Ap + 8 * SA);
                af[mi][2] = *reinterpret_cast<const uint32_t*>(Ap + 8);
                af[mi][3] = *reinterpret_cast<const uint32_t*>(Ap + 8 * SA + 8);
            }
#pragma unroll
            for (int ni = 0; ni < 2; ni++) {
                const __half* Bp = &Bsb[(wc * 16 + ni * 8 + lr) * SA + ks + 2 * lc];
                uint32_t b0 = *reinterpret_cast<const uint32_t*>(Bp);
                uint32_t b1 = *reinterpret_cast<const uint32_t*>(Bp + 8);
#pragma unroll
                for (int mi = 0; mi < 2; mi++)
                    mma_f16(acc[mi][ni], af[mi], b0, b1);
            }
        }
    }

#pragma unroll
    for (int mi = 0; mi < 2; mi++) {
#pragma unroll
        for (int ni = 0; ni < 2; ni++) {
            int r0  = x0 + wr * 32 + mi * 16 + lr;
            int col = n0 + wc * 16 + ni * 8 + 2 * lc;
            float d0 = acc[mi][ni][0], d1 = acc[mi][ni][1];
            float d2 = acc[mi][ni][2], d3 = acc[mi][ni][3];
            *reinterpret_cast<float2*>(&Cf[(size_t)r0 * Y_ + col]) = make_float2(d0, d1);
            *reinterpret_cast<float2*>(&Cf[(size_t)(r0 + 8) * Y_ + col]) = make_float2(d2, d3);
            float c0 = fminf(fmaxf(d0, 1e-6f), 1e5f);
            float c1 = fminf(fmaxf(d1, 1e-6f), 1e5f);
            float c2 = fminf(fmaxf(d2, 1e-6f), 1e5f);
            float c3 = fminf(fmaxf(d3, 1e-6f), 1e5f);
            *reinterpret_cast<float2*>(&ip[(size_t)r0 * Y_ + col]) =
                make_float2(1.0f / c0, 1.0f / c1);
            *reinterpret_cast<float2*>(&ip[(size_t)(r0 + 8) * Y_ + col]) =
                make_float2(1.0f / c2, 1.0f / c3);
        }
    }
}

// ---------------------------------------------------------------------------
extern "C" void kernel_launch(void* const* d_in, const int* in_sizes, int n_in,
                              void* d_out, int out_size) {
    const float* xin_lon  = (const float*)d_in[0];
    const float* xin_lat  = (const float*)d_in[1];
    const float* wt       = (const float*)d_in[2];
    const float* xout_lon = (const float*)d_in[3];
    const float* xout_lat = (const float*)d_in[4];
    const float* init_ls  = (const float*)d_in[5];
    float* out = (float*)d_out;
    (void)in_sizes; (void)n_in; (void)out_size;

    const int nrbf = B_ * X_ * W_ + B_ * Y_ * H_;
    rbf_kernel<<<(nrbf + 255) / 256, 256>>>(xin_lon, xin_lat, xout_lon, xout_lat, init_ls);

    // wt_full transpose+fix: per-channel 256x256, 32x32 tiles
    prep_wt_t<<<dim3(W_ / 32, H_ / 32, B_ * CP1), dim3(32, 8)>>>(wt);

    // Stage A: 66 GEMMs M=512 N=256 K=256 -> g_tmp (fp16)
    mma_gemm<0><<<dim3(H_ / BN, X_ / BM, B_ * CP1), NTH>>>(out);

    // Density stage-B: 64x64 tiles, writes out plane0 + g_invd
    dens_gemm<<<dim3(Y_ / 64, X_ / 64, B_), 256>>>(out);

    // Stage B remaining 32 channels, fused divide
    mma_gemm<2><<<dim3(Y_ / BN, X_ / BM, B_ * C_), NTH>>>(out);
}